// round 1
// baseline (speedup 1.0000x reference)
#include <cuda_runtime.h>
#include <cstdint>

#define NB      32
#define NCH     84
#define NCLS    80
#define NANCH   8400
#define TOPK    1000
#define MAXDET  300
#define SORTN   16384
#define CONF    0.25f
#define IOU_THR 0.7f
#define MAX_WH  7680.0f
#define IMG_SZ  640.0f
#define NEG_BIG (-3.402823466e38f)

// ---------------- scratch (device globals; no allocation allowed) ----------
__device__ float        g_score[NB * NANCH];
__device__ int          g_label[NB * NANCH];
__device__ float        g_box  [NB * NANCH * 4];
__device__ float        g_top_score[NB * TOPK];
__device__ int          g_top_label[NB * TOPK];
__device__ float        g_top_box  [NB * TOPK * 4];
__device__ unsigned char g_keep    [NB * TOPK];

__constant__ int c_coco[80] = {
    1,2,3,4,5,6,7,8,9,10,11,13,14,15,16,17,18,19,20,21,22,23,24,25,27,28,
    31,32,33,34,35,36,37,38,39,40,41,42,43,44,46,47,48,49,50,51,52,53,54,55,
    56,57,58,59,60,61,62,63,64,65,67,70,72,73,74,75,76,77,78,79,80,81,82,84,
    85,86,87,88,89,90
};

// ---------------- stage 1: decode ------------------------------------------
// preds [32, 84, 8400] channel-major. Per (b, anchor): max/argmax over 80
// classes (strict > keeps FIRST max index, matching jnp.argmax), xywh->xyxy
// scaled by 640, masked score (-1 if <= CONF) for the top_k, as reference.
__global__ void __launch_bounds__(256) decode_kernel(const float* __restrict__ preds) {
    int a = blockIdx.x * blockDim.x + threadIdx.x;
    int b = blockIdx.y;
    if (a >= NANCH) return;
    const float* base = preds + (size_t)b * NCH * NANCH + a;

    float x = base[0]          * IMG_SZ;
    float y = base[NANCH]      * IMG_SZ;
    float w = base[2 * NANCH]  * IMG_SZ;
    float h = base[3 * NANCH]  * IMG_SZ;

    float best = base[4 * NANCH];
    int   bi   = 0;
#pragma unroll 4
    for (int c = 1; c < NCLS; c++) {
        float v = base[(4 + c) * NANCH];
        if (v > best) { best = v; bi = c; }
    }

    int o = b * NANCH + a;
    g_score[o] = (best > CONF) ? best : -1.0f;   // s_masked
    g_label[o] = bi;
    float hw = w * 0.5f, hh = h * 0.5f;
    g_box[o * 4 + 0] = x - hw;
    g_box[o * 4 + 1] = y - hh;
    g_box[o * 4 + 2] = x + hw;
    g_box[o * 4 + 3] = y + hh;
}

// ---------------- stage 2: per-batch full bitonic sort, keep top-1000 ------
// Key = (order-preserving uint map of score) << 32 | ~idx
// Sorting keys DESCENDING == (score desc, idx asc) — exactly lax.top_k order.
__device__ __forceinline__ unsigned int fmap(float f) {
    unsigned int u = __float_as_uint(f);
    return (u & 0x80000000u) ? ~u : (u | 0x80000000u);
}

__global__ void __launch_bounds__(1024) sort_kernel() {
    extern __shared__ unsigned long long sk[];   // SORTN keys = 128 KB
    int b   = blockIdx.x;
    int tid = threadIdx.x;

    for (int i = tid; i < SORTN; i += 1024) {
        float s = (i < NANCH) ? g_score[b * NANCH + i] : NEG_BIG;
        sk[i] = ((unsigned long long)fmap(s) << 32) | (unsigned int)(~i);
    }
    __syncthreads();

    for (int k = 2; k <= SORTN; k <<= 1) {
        for (int j = k >> 1; j > 0; j >>= 1) {
            for (int t = tid; t < SORTN / 2; t += 1024) {
                int i = ((t & ~(j - 1)) << 1) | (t & (j - 1));
                int l = i | j;
                unsigned long long a = sk[i], c = sk[l];
                bool desc = ((i & k) == 0);
                if (desc ? (a < c) : (a > c)) { sk[i] = c; sk[l] = a; }
            }
            __syncthreads();
        }
    }

    // gather top-1000
    for (int t = tid; t < TOPK; t += 1024) {
        unsigned int idx = ~(unsigned int)(sk[t] & 0xFFFFFFFFu);
        int o = b * TOPK + t;
        if (idx < NANCH) {
            int src = b * NANCH + (int)idx;
            g_top_score[o]     = g_score[src];
            g_top_label[o]     = g_label[src];
            g_top_box[o*4 + 0] = g_box[src*4 + 0];
            g_top_box[o*4 + 1] = g_box[src*4 + 1];
            g_top_box[o*4 + 2] = g_box[src*4 + 2];
            g_top_box[o*4 + 3] = g_box[src*4 + 3];
        } else {
            g_top_score[o] = -1.0f;
            g_top_label[o] = 0;
            g_top_box[o*4+0] = g_top_box[o*4+1] = g_top_box[o*4+2] = g_top_box[o*4+3] = 0.0f;
        }
    }
}

// ---------------- stage 3: greedy NMS (exact reference semantics) ----------
// keep starts ALL TRUE (no conf gate — reference applies it after NMS).
// Class-offset boxes: box + label*7680 (all 4 coords). iou = inter /
// (area_i + area_j - inter + 1e-7), suppress j>i when iou > 0.7 and keep[i].
__global__ void __launch_bounds__(1024) nms_kernel() {
    int b   = blockIdx.x;
    int tid = threadIdx.x;
    __shared__ float x1[TOPK], y1[TOPK], x2[TOPK], y2[TOPK], ar[TOPK];
    __shared__ unsigned char keep[TOPK];

    for (int t = tid; t < TOPK; t += blockDim.x) {
        int o = b * TOPK + t;
        float off = (float)g_top_label[o] * MAX_WH;
        float a0 = g_top_box[o*4+0] + off;
        float a1 = g_top_box[o*4+1] + off;
        float a2 = g_top_box[o*4+2] + off;
        float a3 = g_top_box[o*4+3] + off;
        x1[t] = a0; y1[t] = a1; x2[t] = a2; y2[t] = a3;
        ar[t] = (a2 - a0) * (a3 - a1);
        keep[t] = 1;
    }
    __syncthreads();

    for (int i = 0; i < TOPK - 1; i++) {
        if (keep[i]) {                       // uniform branch (shared, post-sync)
            float bx1 = x1[i], by1 = y1[i], bx2 = x2[i], by2 = y2[i], ba = ar[i];
            for (int j = i + 1 + tid; j < TOPK; j += blockDim.x) {
                if (keep[j]) {
                    float lx = fmaxf(bx1, x1[j]);
                    float ly = fmaxf(by1, y1[j]);
                    float rx = fminf(bx2, x2[j]);
                    float ry = fminf(by2, y2[j]);
                    float w  = fmaxf(rx - lx, 0.0f);
                    float h  = fmaxf(ry - ly, 0.0f);
                    float inter = w * h;
                    float iou = inter / (ba + ar[j] - inter + 1e-7f);
                    if (iou > IOU_THR) keep[j] = 0;
                }
            }
        }
        __syncthreads();
    }

    for (int t = tid; t < TOPK; t += blockDim.x) {
        int o = b * TOPK + t;
        g_keep[o] = (keep[t] && (g_top_score[o] > CONF)) ? 1 : 0;
    }
}

// ---------------- stage 4: emit top-300 ------------------------------------
// Kept entries are in descending-score order already, so the reference's
// final top_k == take first 300 kept in order; everything else -> 0.
// Output layout (flattened tuple, float): boxes[32*300*4] | scores[32*300] |
// labels[32*300].
__global__ void __launch_bounds__(256) output_kernel(float* __restrict__ out) {
    int b   = blockIdx.x;
    int tid = threadIdx.x;
    float* ob = out + (size_t)b * MAXDET * 4;
    float* os = out + (size_t)NB * MAXDET * 4 + (size_t)b * MAXDET;
    float* ol = out + (size_t)NB * MAXDET * 5 + (size_t)b * MAXDET;

    for (int t = tid; t < MAXDET; t += blockDim.x) {
        ob[t*4+0] = 0.0f; ob[t*4+1] = 0.0f; ob[t*4+2] = 0.0f; ob[t*4+3] = 0.0f;
        os[t] = 0.0f;
        ol[t] = 0.0f;
    }
    __syncthreads();

    if (tid == 0) {
        int cnt = 0;
        for (int t = 0; t < TOPK && cnt < MAXDET; t++) {
            int o = b * TOPK + t;
            if (g_keep[o]) {
                ob[cnt*4+0] = g_top_box[o*4+0];
                ob[cnt*4+1] = g_top_box[o*4+1];
                ob[cnt*4+2] = g_top_box[o*4+2];
                ob[cnt*4+3] = g_top_box[o*4+3];
                os[cnt]     = g_top_score[o];
                ol[cnt]     = (float)c_coco[g_top_label[o]];
                cnt++;
            }
        }
    }
}

// ---------------- launch ----------------------------------------------------
extern "C" void kernel_launch(void* const* d_in, const int* in_sizes, int n_in,
                              void* d_out, int out_size) {
    (void)in_sizes; (void)n_in; (void)out_size;
    const float* preds = (const float*)d_in[0];
    float* out = (float*)d_out;

    cudaFuncSetAttribute(sort_kernel,
                         cudaFuncAttributeMaxDynamicSharedMemorySize,
                         SORTN * sizeof(unsigned long long));

    dim3 dgrid((NANCH + 255) / 256, NB);
    decode_kernel<<<dgrid, 256>>>(preds);
    sort_kernel<<<NB, 1024, SORTN * sizeof(unsigned long long)>>>();
    nms_kernel<<<NB, 1024>>>();
    output_kernel<<<NB, 256>>>(out);
}

// round 2
// speedup vs baseline: 2.8321x; 2.8321x over previous
#include <cuda_runtime.h>
#include <cstdint>

#define NB      32
#define NCH     84
#define NCLS    80
#define NANCH   8400
#define TOPK    1000
#define MAXDET  300
#define CONF    0.25f
#define IOU_THR 0.7f
#define MAX_WH  7680.0f
#define IMG_SZ  640.0f

// ---------------- scratch (device globals; no allocation allowed) ----------
__device__ float              g_score[NB * NANCH];
__device__ int                g_label[NB * NANCH];
__device__ float              g_box  [NB * NANCH * 4];
__device__ float              g_top_score[NB * TOPK];
__device__ int                g_top_label[NB * TOPK];
__device__ float              g_top_box  [NB * TOPK * 4];
__device__ unsigned long long g_sup      [(size_t)NB * TOPK * 16];  // 4 MB bitmatrix

__constant__ int c_coco[80] = {
    1,2,3,4,5,6,7,8,9,10,11,13,14,15,16,17,18,19,20,21,22,23,24,25,27,28,
    31,32,33,34,35,36,37,38,39,40,41,42,43,44,46,47,48,49,50,51,52,53,54,55,
    56,57,58,59,60,61,62,63,64,65,67,70,72,73,74,75,76,77,78,79,80,81,82,84,
    85,86,87,88,89,90
};

// ---------------- stage 1: decode ------------------------------------------
// preds [32, 84, 8400] channel-major. Strict > argmax keeps FIRST max index
// (matches jnp.argmax). Score masked to -1 if <= CONF (matches s_masked).
__global__ void __launch_bounds__(256) decode_kernel(const float* __restrict__ preds) {
    int a = blockIdx.x * blockDim.x + threadIdx.x;
    int b = blockIdx.y;
    if (a >= NANCH) return;
    const float* base = preds + (size_t)b * NCH * NANCH + a;

    float x = base[0]          * IMG_SZ;
    float y = base[NANCH]      * IMG_SZ;
    float w = base[2 * NANCH]  * IMG_SZ;
    float h = base[3 * NANCH]  * IMG_SZ;

    float best = base[4 * NANCH];
    int   bi   = 0;
#pragma unroll 4
    for (int c = 1; c < NCLS; c++) {
        float v = base[(4 + c) * NANCH];
        if (v > best) { best = v; bi = c; }
    }

    int o = b * NANCH + a;
    g_score[o] = (best > CONF) ? best : -1.0f;
    g_label[o] = bi;
    float hw = w * 0.5f, hh = h * 0.5f;
    float4 bx = make_float4(x - hw, y - hh, x + hw, y + hh);
    ((float4*)g_box)[o] = bx;
}

// ---------------- stage 2: exact top-1000 via radix select + 1K sort -------
// 64-bit key = (order-preserving uint of score) << 32 | ~idx. Keys distinct
// (low bits), so 8-pass MSD radix select yields the exact 1000th-largest key;
// exactly TOPK keys are >= it. Compact those and bitonic-sort 1024.
__device__ __forceinline__ unsigned int fmap(float f) {
    unsigned int u = __float_as_uint(f);
    return (u & 0x80000000u) ? ~u : (u | 0x80000000u);
}

#define SEL_SMEM ((8448 + 1024) * 8)

__global__ void __launch_bounds__(1024) select_kernel() {
    extern __shared__ unsigned long long sm[];
    unsigned long long* key  = sm;          // 8400 used (8448 slot pad)
    unsigned long long* cand = sm + 8448;   // 1024
    __shared__ int hist[256];
    __shared__ unsigned long long s_prefix;
    __shared__ int s_k, s_cnt;

    int b = blockIdx.x, tid = threadIdx.x;

    for (int i = tid; i < NANCH; i += 1024) {
        float s = g_score[b * NANCH + i];
        key[i] = ((unsigned long long)fmap(s) << 32) | (unsigned int)(~i);
    }
    if (tid == 0) { s_prefix = 0ull; s_k = TOPK; s_cnt = 0; }
    __syncthreads();

    for (int pass = 0; pass < 8; ++pass) {
        if (tid < 256) hist[tid] = 0;
        __syncthreads();
        unsigned long long pfx = s_prefix;
        int shift = 56 - 8 * pass;
        for (int i = tid; i < NANCH; i += 1024) {
            unsigned long long v = key[i];
            bool act = (pass == 0) || ((v >> (shift + 8)) == pfx);
            if (act) atomicAdd(&hist[(int)((v >> shift) & 255ull)], 1);
        }
        __syncthreads();
        if (tid == 0) {
            int k = s_k, d = 255;
            for (;; --d) { int h = hist[d]; if (h >= k) break; k -= h; }
            s_prefix = (pfx << 8) | (unsigned long long)d;
            s_k = k;
        }
        __syncthreads();
    }

    // exactly TOPK keys >= s_prefix
    unsigned long long thr = s_prefix;
    for (int i = tid; i < NANCH; i += 1024) {
        unsigned long long v = key[i];
        if (v >= thr) { int p = atomicAdd(&s_cnt, 1); cand[p] = v; }
    }
    __syncthreads();
    if (tid < 1024 - TOPK) cand[TOPK + tid] = 0ull;   // pad sorts last
    __syncthreads();

    // bitonic sort 1024 descending (64-bit keys)
    for (int kk = 2; kk <= 1024; kk <<= 1) {
        for (int j = kk >> 1; j > 0; j >>= 1) {
            if (tid < 512) {
                int i = ((tid & ~(j - 1)) << 1) | (tid & (j - 1));
                int l = i | j;
                unsigned long long a = cand[i], c = cand[l];
                bool desc = ((i & kk) == 0);
                if (desc ? (a < c) : (a > c)) { cand[i] = c; cand[l] = a; }
            }
            __syncthreads();
        }
    }

    if (tid < TOPK) {
        unsigned int idx = ~(unsigned int)(cand[tid] & 0xFFFFFFFFull);
        int src = b * NANCH + (int)idx;
        int o   = b * TOPK + tid;
        g_top_score[o] = g_score[src];
        g_top_label[o] = g_label[src];
        ((float4*)g_top_box)[o] = ((const float4*)g_box)[src];
    }
}

// ---------------- stage 3a: suppression bitmatrix ---------------------------
// sup[i][w] bit j: (j > i) && iou(i,j) > 0.7 on class-offset boxes.
// Same arithmetic as the verified R1 kernel.
__global__ void __launch_bounds__(1024) supbuild_kernel() {
    __shared__ float sx1[TOPK], sy1[TOPK], sx2[TOPK], sy2[TOPK], sar[TOPK];
    int b = blockIdx.y, slice = blockIdx.x, tid = threadIdx.x;
    const int ROWS_PER = TOPK / 8;   // 125

    for (int t = tid; t < TOPK; t += 1024) {
        int o = b * TOPK + t;
        float off = (float)g_top_label[o] * MAX_WH;
        float4 bx = ((const float4*)g_top_box)[o];
        float a0 = bx.x + off, a1 = bx.y + off, a2 = bx.z + off, a3 = bx.w + off;
        sx1[t] = a0; sy1[t] = a1; sx2[t] = a2; sy2[t] = a3;
        sar[t] = (a2 - a0) * (a3 - a1);
    }
    __syncthreads();

    for (int t = tid; t < ROWS_PER * 16; t += 1024) {
        int r = slice * ROWS_PER + (t % ROWS_PER);   // consecutive threads: same w, consecutive r
        int w = t / ROWS_PER;
        float bx1 = sx1[r], by1 = sy1[r], bx2 = sx2[r], by2 = sy2[r], ba = sar[r];
        unsigned long long m = 0;
        int j0 = w * 64;
#pragma unroll 4
        for (int bb = 0; bb < 64; ++bb) {
            int j = j0 + bb;
            if (j > r && j < TOPK) {
                float lx = fmaxf(bx1, sx1[j]);
                float ly = fmaxf(by1, sy1[j]);
                float rx = fminf(bx2, sx2[j]);
                float ry = fminf(by2, sy2[j]);
                float wd = fmaxf(rx - lx, 0.0f);
                float ht = fmaxf(ry - ly, 0.0f);
                float inter = wd * ht;
                float iou = inter / (ba + sar[j] - inter + 1e-7f);
                if (iou > IOU_THR) m |= (1ull << bb);
            }
        }
        g_sup[((size_t)b * TOPK + r) * 16 + w] = m;
    }
}

// ---------------- stage 3b: resolve + compact + emit ------------------------
// Warp 0 does the (inherently sequential) greedy resolution bit-serially:
// lane w owns keep word w; only currently-kept bits are visited. Then a
// ballot-scan compacts the first 300 kept (already score-descending ==
// reference's final top_k) into the output.
#define RES_SMEM (TOPK * 16 * 8)

__global__ void __launch_bounds__(1024) resolve_kernel(float* __restrict__ out) {
    extern __shared__ unsigned long long s_sup[];   // 16000 words = 128 KB
    __shared__ unsigned long long keepw_s[16];
    __shared__ int wtot[32], woff[32];

    int b = blockIdx.x, tid = threadIdx.x;
    int wid = tid >> 5, lane = tid & 31;

    float* ob = out + (size_t)b * MAXDET * 4;
    float* os = out + (size_t)NB * MAXDET * 4 + (size_t)b * MAXDET;
    float* ol = out + (size_t)NB * MAXDET * 5 + (size_t)b * MAXDET;

    // zero-fill output slots (d_out is poisoned)
    for (int t = tid; t < MAXDET; t += 1024) {
        ((float4*)ob)[t] = make_float4(0.f, 0.f, 0.f, 0.f);
        os[t] = 0.0f;
        ol[t] = 0.0f;
    }

    const unsigned long long* gs = g_sup + (size_t)b * TOPK * 16;
    for (int i = tid; i < TOPK * 16; i += 1024) s_sup[i] = gs[i];
    __syncthreads();

    if (tid < 32) {
        unsigned long long kw = ~0ull;
        for (int w = 0; w < 16; ++w) {
            unsigned long long done = 0;
            while (true) {
                unsigned long long cur = __shfl_sync(0xFFFFFFFFu, kw, w);
                unsigned long long rem = cur & ~done;
                if (!rem) break;
                int bit = __ffsll((long long)rem) - 1;
                done = (bit == 63) ? ~0ull : ((1ull << (bit + 1)) - 1ull);
                int i = w * 64 + bit;
                if (i < TOPK) {
                    unsigned long long s = (lane < 16) ? s_sup[i * 16 + lane] : 0ull;
                    kw &= ~s;
                }
            }
        }
        if (lane < 16) keepw_s[lane] = kw;
    }
    __syncthreads();

    // flags (NMS keep & conf gate), block-wide exclusive scan, scatter
    int f = 0;
    float sc = 0.0f;
    if (tid < TOPK) {
        sc = g_top_score[b * TOPK + tid];
        f = (int)((keepw_s[tid >> 6] >> (tid & 63)) & 1ull) & (sc > CONF ? 1 : 0);
    }
    unsigned bal = __ballot_sync(0xFFFFFFFFu, f);
    if (lane == 0) wtot[wid] = __popc(bal);
    __syncthreads();
    if (tid == 0) {
        int acc = 0;
        for (int i = 0; i < 32; i++) { woff[i] = acc; acc += wtot[i]; }
    }
    __syncthreads();
    int pos = woff[wid] + __popc(bal & ((1u << lane) - 1u));

    if (f && pos < MAXDET) {
        int o = b * TOPK + tid;
        ((float4*)ob)[pos] = ((const float4*)g_top_box)[o];
        os[pos] = sc;
        ol[pos] = (float)c_coco[g_top_label[o]];
    }
}

// ---------------- launch ----------------------------------------------------
extern "C" void kernel_launch(void* const* d_in, const int* in_sizes, int n_in,
                              void* d_out, int out_size) {
    (void)in_sizes; (void)n_in; (void)out_size;
    const float* preds = (const float*)d_in[0];
    float* out = (float*)d_out;

    cudaFuncSetAttribute(select_kernel,
                         cudaFuncAttributeMaxDynamicSharedMemorySize, SEL_SMEM);
    cudaFuncSetAttribute(resolve_kernel,
                         cudaFuncAttributeMaxDynamicSharedMemorySize, RES_SMEM);

    dim3 dgrid((NANCH + 255) / 256, NB);
    decode_kernel<<<dgrid, 256>>>(preds);
    select_kernel<<<NB, 1024, SEL_SMEM>>>();
    supbuild_kernel<<<dim3(8, NB), 1024>>>();
    resolve_kernel<<<NB, 1024, RES_SMEM>>>(out);
}

// round 3
// speedup vs baseline: 3.9756x; 1.4038x over previous
#include <cuda_runtime.h>
#include <cstdint>

#define NB      32
#define NCH     84
#define NCLS    80
#define NANCH   8400
#define TOPK    1000
#define MAXDET  300
#define CONF    0.25f
#define IOU_THR 0.7f
#define MAX_WH  7680.0f
#define IMG_SZ  640.0f

// ---------------- scratch (device globals; no allocation allowed) ----------
__device__ float              g_score[NB * NANCH];
__device__ int                g_label[NB * NANCH];
__device__ float              g_box  [NB * NANCH * 4];
__device__ float              g_top_score[NB * TOPK];
__device__ int                g_top_label[NB * TOPK];
__device__ float              g_top_box  [NB * TOPK * 4];
// transposed suppression matrix, word-major: supT[b][w][r] bit bb = i=w*64+bb
// suppresses r (i < r, iou > 0.7). Layout gives coalesced per-thread row loads.
__device__ unsigned long long g_supT[(size_t)NB * 16 * TOPK];

__constant__ int c_coco[80] = {
    1,2,3,4,5,6,7,8,9,10,11,13,14,15,16,17,18,19,20,21,22,23,24,25,27,28,
    31,32,33,34,35,36,37,38,39,40,41,42,43,44,46,47,48,49,50,51,52,53,54,55,
    56,57,58,59,60,61,62,63,64,65,67,70,72,73,74,75,76,77,78,79,80,81,82,84,
    85,86,87,88,89,90
};

// ---------------- stage 1: decode ------------------------------------------
__global__ void __launch_bounds__(256) decode_kernel(const float* __restrict__ preds) {
    int a = blockIdx.x * blockDim.x + threadIdx.x;
    int b = blockIdx.y;
    if (a >= NANCH) return;
    const float* base = preds + (size_t)b * NCH * NANCH + a;

    float x = base[0]          * IMG_SZ;
    float y = base[NANCH]      * IMG_SZ;
    float w = base[2 * NANCH]  * IMG_SZ;
    float h = base[3 * NANCH]  * IMG_SZ;

    float best = base[4 * NANCH];
    int   bi   = 0;
#pragma unroll 4
    for (int c = 1; c < NCLS; c++) {
        float v = base[(4 + c) * NANCH];
        if (v > best) { best = v; bi = c; }
    }

    int o = b * NANCH + a;
    g_score[o] = (best > CONF) ? best : -1.0f;
    g_label[o] = bi;
    float hw = w * 0.5f, hh = h * 0.5f;
    ((float4*)g_box)[o] = make_float4(x - hw, y - hh, x + hw, y + hh);
}

// ---------------- stage 2: exact top-1000 via radix select + 1K sort -------
// Key = (order-preserving uint of score) << 32 | ~idx  (all keys distinct).
// 6 radix passes: 4 on the score word, then bits 31:16 of the low word are
// always 0xFFFF (idx < 8400 => ~idx >> 16 == 0xFFFF), then 2 on bits 15:0.
// Histogram atomics warp-aggregated via __match_any_sync.
__device__ __forceinline__ unsigned int fmap(float f) {
    unsigned int u = __float_as_uint(f);
    return (u & 0x80000000u) ? ~u : (u | 0x80000000u);
}

#define SEL_SMEM ((8448 + 1024) * 8)

__global__ void __launch_bounds__(1024) select_kernel() {
    extern __shared__ unsigned long long sm[];
    unsigned long long* key  = sm;          // 8400 (8448 pad)
    unsigned long long* cand = sm + 8448;   // 1024
    __shared__ int hist[256];
    __shared__ unsigned long long s_prefix;
    __shared__ int s_k, s_cnt;

    int b = blockIdx.x, tid = threadIdx.x;
    int lane = tid & 31;

    for (int i = tid; i < NANCH; i += 1024) {
        float s = g_score[b * NANCH + i];
        key[i] = ((unsigned long long)fmap(s) << 32) | (unsigned int)(~i);
    }
    if (tid == 0) { s_prefix = 0ull; s_k = TOPK; s_cnt = 0; }
    __syncthreads();

    const int shifts[6] = {56, 48, 40, 32, 8, 0};
#pragma unroll 1
    for (int pass = 0; pass < 6; ++pass) {
        if (tid < 256) hist[tid] = 0;
        __syncthreads();
        unsigned long long pfx = s_prefix;
        int shift = shifts[pass];
#pragma unroll 1
        for (int ii = 0; ii < 9; ++ii) {           // 9*1024 >= 8400, full warps
            int i = tid + ii * 1024;
            unsigned long long v = (i < NANCH) ? key[i] : 0ull;
            bool act = (i < NANCH) &&
                       ((pass == 0) || ((v >> (shift + 8)) == pfx));
            int bin = act ? (int)((v >> shift) & 255ull) : (300 + lane);
            unsigned grp = __match_any_sync(0xFFFFFFFFu, bin);
            if (act && lane == (__ffs(grp) - 1))
                atomicAdd(&hist[bin], __popc(grp));
        }
        __syncthreads();
        if (tid == 0) {
            int k = s_k, d = 255;
            for (;; --d) { int h = hist[d]; if (h >= k) break; k -= h; }
            unsigned long long np = (pfx << 8) | (unsigned long long)d;
            if (pass == 3) np = (np << 16) | 0xFFFFull;  // known ~idx high bits
            s_prefix = np;
            s_k = k;
        }
        __syncthreads();
    }

    unsigned long long thr = s_prefix;   // exact 1000th-largest key
    for (int i = tid; i < NANCH; i += 1024) {
        unsigned long long v = key[i];
        if (v >= thr) { int p = atomicAdd(&s_cnt, 1); cand[p] = v; }
    }
    __syncthreads();
    if (tid < 1024 - TOPK) cand[TOPK + tid] = 0ull;
    __syncthreads();

    // bitonic sort 1024 descending
    for (int kk = 2; kk <= 1024; kk <<= 1) {
        for (int j = kk >> 1; j > 0; j >>= 1) {
            if (tid < 512) {
                int i = ((tid & ~(j - 1)) << 1) | (tid & (j - 1));
                int l = i | j;
                unsigned long long a = cand[i], c = cand[l];
                bool desc = ((i & kk) == 0);
                if (desc ? (a < c) : (a > c)) { cand[i] = c; cand[l] = a; }
            }
            __syncthreads();
        }
    }

    if (tid < TOPK) {
        unsigned int idx = ~(unsigned int)(cand[tid] & 0xFFFFFFFFull);
        int src = b * NANCH + (int)idx;
        int o   = b * TOPK + tid;
        g_top_score[o] = g_score[src];
        g_top_label[o] = g_label[src];
        ((float4*)g_top_box)[o] = ((const float4*)g_box)[src];
    }
}

// ---------------- stage 3a: transposed suppression bitmatrix ---------------
// supT[b][w][r] bit bb: i = w*64+bb, set iff i < r && iou(i, r) > 0.7.
// IoU arithmetic identical to verified R1/R2 (commutative fp ops).
__global__ void __launch_bounds__(1024) supbuild_kernel() {
    __shared__ float sx1[TOPK], sy1[TOPK], sx2[TOPK], sy2[TOPK], sar[TOPK];
    int b = blockIdx.y, slice = blockIdx.x, tid = threadIdx.x;
    const int ROWS_PER = TOPK / 8;   // 125

    for (int t = tid; t < TOPK; t += 1024) {
        int o = b * TOPK + t;
        float off = (float)g_top_label[o] * MAX_WH;
        float4 bx = ((const float4*)g_top_box)[o];
        float a0 = bx.x + off, a1 = bx.y + off, a2 = bx.z + off, a3 = bx.w + off;
        sx1[t] = a0; sy1[t] = a1; sx2[t] = a2; sy2[t] = a3;
        sar[t] = (a2 - a0) * (a3 - a1);
    }
    __syncthreads();

    for (int t = tid; t < ROWS_PER * 16; t += 1024) {
        int r = slice * ROWS_PER + (t % ROWS_PER);
        int w = t / ROWS_PER;
        float bx1 = sx1[r], by1 = sy1[r], bx2 = sx2[r], by2 = sy2[r], ba = sar[r];
        unsigned long long m = 0;
        int j0 = w * 64;
#pragma unroll 4
        for (int bb = 0; bb < 64; ++bb) {
            int i = j0 + bb;
            if (i < r) {
                float lx = fmaxf(bx1, sx1[i]);
                float ly = fmaxf(by1, sy1[i]);
                float rx = fminf(bx2, sx2[i]);
                float ry = fminf(by2, sy2[i]);
                float wd = fmaxf(rx - lx, 0.0f);
                float ht = fmaxf(ry - ly, 0.0f);
                float inter = wd * ht;
                float iou = inter / (ba + sar[i] - inter + 1e-7f);
                if (iou > IOU_THR) m |= (1ull << bb);
            }
        }
        g_supT[((size_t)b * 16 + w) * TOPK + r] = m;
    }
}

// ---------------- stage 3b: Jacobi-fixpoint resolve + compact + emit --------
// keep[j] = !exists i<j: keep[i] && sup[i][j], iterated from all-true.
// Converges to the exact greedy NMS result in (max chain depth + 1) parallel
// iterations; fixpoint is unique. Thread j holds its supT row in registers.
__global__ void __launch_bounds__(1024) resolve_kernel(float* __restrict__ out) {
    __shared__ unsigned long long kbuf[2][16];
    __shared__ int s_changed;

    int b = blockIdx.x, tid = threadIdx.x;
    int wid = tid >> 5, lane = tid & 31;

    float* ob = out + (size_t)b * MAXDET * 4;
    float* os = out + (size_t)NB * MAXDET * 4 + (size_t)b * MAXDET;
    float* ol = out + (size_t)NB * MAXDET * 5 + (size_t)b * MAXDET;

    for (int t = tid; t < MAXDET; t += 1024) {
        ((float4*)ob)[t] = make_float4(0.f, 0.f, 0.f, 0.f);
        os[t] = 0.0f;
        ol[t] = 0.0f;
    }

    // per-thread transposed sup row (registers); coalesced loads
    unsigned long long r[16];
    const unsigned long long* gs = g_supT + (size_t)b * 16 * TOPK;
#pragma unroll
    for (int w = 0; w < 16; ++w)
        r[w] = (tid < TOPK) ? gs[w * TOPK + tid] : 0ull;

    if (tid == 0) s_changed = 0;
    if (tid < 32) ((unsigned int*)kbuf[0])[tid] = 0xFFFFFFFFu;
    __syncthreads();

    int cur = 0;
#pragma unroll 1
    for (int it = 0; it < 1001; ++it) {
        bool suppressed = false;
#pragma unroll
        for (int w = 0; w < 16; ++w)
            suppressed |= (r[w] & kbuf[cur][w]) != 0ull;   // broadcast LDS
        unsigned bal = __ballot_sync(0xFFFFFFFFu, !suppressed);
        if (lane == 0) {
            unsigned old = ((unsigned int*)kbuf[cur])[wid];
            ((unsigned int*)kbuf[cur ^ 1])[wid] = bal;
            if (bal != old) s_changed = 1;
        }
        __syncthreads();
        int ch = s_changed;
        __syncthreads();
        if (!ch) break;            // uniform
        if (tid == 0) s_changed = 0;
        cur ^= 1;
        __syncthreads();
    }

    // conf gate + block scan + scatter (kept are already score-descending)
    __shared__ int wtot[32], woff[32];
    int f = 0;
    float sc = 0.0f;
    if (tid < TOPK) {
        sc = g_top_score[b * TOPK + tid];
        f = (int)((kbuf[cur][tid >> 6] >> (tid & 63)) & 1ull) & (sc > CONF ? 1 : 0);
    }
    unsigned bal = __ballot_sync(0xFFFFFFFFu, f);
    if (lane == 0) wtot[wid] = __popc(bal);
    __syncthreads();
    if (tid == 0) {
        int acc = 0;
        for (int i = 0; i < 32; i++) { woff[i] = acc; acc += wtot[i]; }
    }
    __syncthreads();
    int pos = woff[wid] + __popc(bal & ((1u << lane) - 1u));

    if (f && pos < MAXDET) {
        int o = b * TOPK + tid;
        ((float4*)ob)[pos] = ((const float4*)g_top_box)[o];
        os[pos] = sc;
        ol[pos] = (float)c_coco[g_top_label[o]];
    }
}

// ---------------- launch ----------------------------------------------------
extern "C" void kernel_launch(void* const* d_in, const int* in_sizes, int n_in,
                              void* d_out, int out_size) {
    (void)in_sizes; (void)n_in; (void)out_size;
    const float* preds = (const float*)d_in[0];
    float* out = (float*)d_out;

    cudaFuncSetAttribute(select_kernel,
                         cudaFuncAttributeMaxDynamicSharedMemorySize, SEL_SMEM);

    dim3 dgrid((NANCH + 255) / 256, NB);
    decode_kernel<<<dgrid, 256>>>(preds);
    select_kernel<<<NB, 1024, SEL_SMEM>>>();
    supbuild_kernel<<<dim3(8, NB), 1024>>>();
    resolve_kernel<<<NB, 1024>>>(out);
}

// round 4
// speedup vs baseline: 5.2326x; 1.3162x over previous
#include <cuda_runtime.h>
#include <cstdint>

#define NB      32
#define NCH     84
#define NCLS    80
#define NANCH   8400
#define TOPK    1000
#define MAXDET  300
#define CONF    0.25f
#define IOU_THR 0.7f
#define MAX_WH  7680.0f
#define IMG_SZ  640.0f

// ---------------- scratch (device globals; no allocation allowed) ----------
__device__ float              g_score[NB * NANCH];
__device__ int                g_label[NB * NANCH];
__device__ float              g_box  [NB * NANCH * 4];
__device__ float              g_top_score[NB * TOPK];
__device__ int                g_top_label[NB * TOPK];
__device__ float              g_top_box  [NB * TOPK * 4];
// transposed suppression matrix, word-major: supT[b][w][r] bit bb = i=w*64+bb
// suppresses r (i < r, iou > 0.7).
__device__ unsigned long long g_supT[(size_t)NB * 16 * TOPK];

__constant__ int c_coco[80] = {
    1,2,3,4,5,6,7,8,9,10,11,13,14,15,16,17,18,19,20,21,22,23,24,25,27,28,
    31,32,33,34,35,36,37,38,39,40,41,42,43,44,46,47,48,49,50,51,52,53,54,55,
    56,57,58,59,60,61,62,63,64,65,67,70,72,73,74,75,76,77,78,79,80,81,82,84,
    85,86,87,88,89,90
};

// ---------------- stage 1: decode ------------------------------------------
__global__ void __launch_bounds__(256) decode_kernel(const float* __restrict__ preds) {
    int a = blockIdx.x * blockDim.x + threadIdx.x;
    int b = blockIdx.y;
    if (a >= NANCH) return;
    const float* base = preds + (size_t)b * NCH * NANCH + a;

    float x = base[0]          * IMG_SZ;
    float y = base[NANCH]      * IMG_SZ;
    float w = base[2 * NANCH]  * IMG_SZ;
    float h = base[3 * NANCH]  * IMG_SZ;

    float best = base[4 * NANCH];
    int   bi   = 0;
#pragma unroll 4
    for (int c = 1; c < NCLS; c++) {
        float v = base[(4 + c) * NANCH];
        if (v > best) { best = v; bi = c; }
    }

    int o = b * NANCH + a;
    g_score[o] = (best > CONF) ? best : -1.0f;
    g_label[o] = bi;
    float hw = w * 0.5f, hh = h * 0.5f;
    ((float4*)g_box)[o] = make_float4(x - hw, y - hh, x + hw, y + hh);
}

// ---------------- stage 2: exact top-1000 via radix select + 1K sort -------
__device__ __forceinline__ unsigned int fmap(float f) {
    unsigned int u = __float_as_uint(f);
    return (u & 0x80000000u) ? ~u : (u | 0x80000000u);
}

#define SEL_SMEM ((8448 + 1024) * 8)

__global__ void __launch_bounds__(1024) select_kernel() {
    extern __shared__ unsigned long long sm[];
    unsigned long long* key  = sm;          // 8400 (8448 pad)
    unsigned long long* cand = sm + 8448;   // 1024
    __shared__ int hist[256];
    __shared__ unsigned long long s_prefix;
    __shared__ int s_k, s_cnt;

    int b = blockIdx.x, tid = threadIdx.x;
    int lane = tid & 31;

    for (int i = tid; i < NANCH; i += 1024) {
        float s = g_score[b * NANCH + i];
        key[i] = ((unsigned long long)fmap(s) << 32) | (unsigned int)(~i);
    }
    if (tid == 0) { s_prefix = 0ull; s_k = TOPK; s_cnt = 0; }
    __syncthreads();

    const int shifts[6] = {56, 48, 40, 32, 8, 0};
#pragma unroll 1
    for (int pass = 0; pass < 6; ++pass) {
        if (tid < 256) hist[tid] = 0;
        __syncthreads();
        unsigned long long pfx = s_prefix;
        int shift = shifts[pass];
#pragma unroll 1
        for (int ii = 0; ii < 9; ++ii) {
            int i = tid + ii * 1024;
            unsigned long long v = (i < NANCH) ? key[i] : 0ull;
            bool act = (i < NANCH) &&
                       ((pass == 0) || ((v >> (shift + 8)) == pfx));
            int bin = act ? (int)((v >> shift) & 255ull) : (300 + lane);
            unsigned grp = __match_any_sync(0xFFFFFFFFu, bin);
            if (act && lane == (__ffs(grp) - 1))
                atomicAdd(&hist[bin], __popc(grp));
        }
        __syncthreads();
        if (tid == 0) {
            int k = s_k, d = 255;
            for (;; --d) { int h = hist[d]; if (h >= k) break; k -= h; }
            unsigned long long np = (pfx << 8) | (unsigned long long)d;
            if (pass == 3) np = (np << 16) | 0xFFFFull;
            s_prefix = np;
            s_k = k;
        }
        __syncthreads();
    }

    unsigned long long thr = s_prefix;
    for (int i = tid; i < NANCH; i += 1024) {
        unsigned long long v = key[i];
        if (v >= thr) { int p = atomicAdd(&s_cnt, 1); cand[p] = v; }
    }
    __syncthreads();
    if (tid < 1024 - TOPK) cand[TOPK + tid] = 0ull;
    __syncthreads();

    for (int kk = 2; kk <= 1024; kk <<= 1) {
        for (int j = kk >> 1; j > 0; j >>= 1) {
            if (tid < 512) {
                int i = ((tid & ~(j - 1)) << 1) | (tid & (j - 1));
                int l = i | j;
                unsigned long long a = cand[i], c = cand[l];
                bool desc = ((i & kk) == 0);
                if (desc ? (a < c) : (a > c)) { cand[i] = c; cand[l] = a; }
            }
            __syncthreads();
        }
    }

    if (tid < TOPK) {
        unsigned int idx = ~(unsigned int)(cand[tid] & 0xFFFFFFFFull);
        int src = b * NANCH + (int)idx;
        int o   = b * TOPK + tid;
        g_top_score[o] = g_score[src];
        g_top_label[o] = g_label[src];
        ((float4*)g_top_box)[o] = ((const float4*)g_box)[src];
    }
}

// ---------------- stage 3a: transposed suppression bitmatrix ---------------
// Division-free, bit-exact: RN(inter/denom) > 0.7f is decided by the interval
// test inter >?< 0.7f*denom*(1 +/- 1e-6); the margin dwarfs combined mul+div
// rounding (~2.4e-7), so outside the band the answer provably equals the
// reference's divide-then-compare. Inside the band (expected ~never) we do
// the exact division. Strictly-lower-triangular: word w of row r is zero when
// 64w >= r, and the bb loop is clipped to r - j0.
__global__ void __launch_bounds__(1024) supbuild_kernel() {
    __shared__ float sx1[TOPK], sy1[TOPK], sx2[TOPK], sy2[TOPK], sar[TOPK];
    int b = blockIdx.y, slice = blockIdx.x, tid = threadIdx.x;
    const int ROWS_PER = TOPK / 8;   // 125

    for (int t = tid; t < TOPK; t += 1024) {
        int o = b * TOPK + t;
        float off = (float)g_top_label[o] * MAX_WH;
        float4 bx = ((const float4*)g_top_box)[o];
        float a0 = bx.x + off, a1 = bx.y + off, a2 = bx.z + off, a3 = bx.w + off;
        sx1[t] = a0; sy1[t] = a1; sx2[t] = a2; sy2[t] = a3;
        sar[t] = (a2 - a0) * (a3 - a1);
    }
    __syncthreads();

    const float HI = 0.7000007f;   // 0.7f * (1 + 1e-6)
    const float LO = 0.6999993f;   // 0.7f * (1 - 1e-6)

    for (int t = tid; t < ROWS_PER * 16; t += 1024) {
        int r = slice * ROWS_PER + (t % ROWS_PER);
        int w = t / ROWS_PER;
        int j0 = w * 64;
        size_t dst = ((size_t)b * 16 + w) * TOPK + r;
        if (j0 >= r) { g_supT[dst] = 0ull; continue; }

        float bx1 = sx1[r], by1 = sy1[r], bx2 = sx2[r], by2 = sy2[r], ba = sar[r];
        unsigned long long m = 0;
        int nbb = min(64, r - j0);
#pragma unroll 4
        for (int bb = 0; bb < nbb; ++bb) {
            int i = j0 + bb;
            float lx = fmaxf(bx1, sx1[i]);
            float ly = fmaxf(by1, sy1[i]);
            float rx = fminf(bx2, sx2[i]);
            float ry = fminf(by2, sy2[i]);
            float wd = fmaxf(rx - lx, 0.0f);
            float ht = fmaxf(ry - ly, 0.0f);
            float inter = wd * ht;
            float denom = ba + sar[i] - inter + 1e-7f;
            bool sup;
            if (inter > HI * denom)       sup = true;
            else if (inter < LO * denom)  sup = false;
            else                          sup = (inter / denom) > IOU_THR; // exact, ~never
            if (sup) m |= (1ull << bb);
        }
        g_supT[dst] = m;
    }
}

// ---------------- stage 3b: Jacobi-fixpoint resolve + compact + emit --------
__global__ void __launch_bounds__(1024) resolve_kernel(float* __restrict__ out) {
    __shared__ unsigned long long kbuf[2][16];
    __shared__ int s_changed;

    int b = blockIdx.x, tid = threadIdx.x;
    int wid = tid >> 5, lane = tid & 31;

    float* ob = out + (size_t)b * MAXDET * 4;
    float* os = out + (size_t)NB * MAXDET * 4 + (size_t)b * MAXDET;
    float* ol = out + (size_t)NB * MAXDET * 5 + (size_t)b * MAXDET;

    for (int t = tid; t < MAXDET; t += 1024) {
        ((float4*)ob)[t] = make_float4(0.f, 0.f, 0.f, 0.f);
        os[t] = 0.0f;
        ol[t] = 0.0f;
    }

    unsigned long long r[16];
    const unsigned long long* gs = g_supT + (size_t)b * 16 * TOPK;
#pragma unroll
    for (int w = 0; w < 16; ++w)
        r[w] = (tid < TOPK) ? gs[w * TOPK + tid] : 0ull;

    if (tid == 0) s_changed = 0;
    if (tid < 32) ((unsigned int*)kbuf[0])[tid] = 0xFFFFFFFFu;
    __syncthreads();

    int cur = 0;
#pragma unroll 1
    for (int it = 0; it < 1001; ++it) {
        bool suppressed = false;
#pragma unroll
        for (int w = 0; w < 16; ++w)
            suppressed |= (r[w] & kbuf[cur][w]) != 0ull;
        unsigned bal = __ballot_sync(0xFFFFFFFFu, !suppressed);
        if (lane == 0) {
            unsigned old = ((unsigned int*)kbuf[cur])[wid];
            ((unsigned int*)kbuf[cur ^ 1])[wid] = bal;
            if (bal != old) s_changed = 1;
        }
        __syncthreads();
        int ch = s_changed;
        __syncthreads();
        if (!ch) break;
        if (tid == 0) s_changed = 0;
        cur ^= 1;
        __syncthreads();
    }

    __shared__ int wtot[32], woff[32];
    int f = 0;
    float sc = 0.0f;
    if (tid < TOPK) {
        sc = g_top_score[b * TOPK + tid];
        f = (int)((kbuf[cur][tid >> 6] >> (tid & 63)) & 1ull) & (sc > CONF ? 1 : 0);
    }
    unsigned bal = __ballot_sync(0xFFFFFFFFu, f);
    if (lane == 0) wtot[wid] = __popc(bal);
    __syncthreads();
    if (tid == 0) {
        int acc = 0;
        for (int i = 0; i < 32; i++) { woff[i] = acc; acc += wtot[i]; }
    }
    __syncthreads();
    int pos = woff[wid] + __popc(bal & ((1u << lane) - 1u));

    if (f && pos < MAXDET) {
        int o = b * TOPK + tid;
        ((float4*)ob)[pos] = ((const float4*)g_top_box)[o];
        os[pos] = sc;
        ol[pos] = (float)c_coco[g_top_label[o]];
    }
}

// ---------------- launch ----------------------------------------------------
extern "C" void kernel_launch(void* const* d_in, const int* in_sizes, int n_in,
                              void* d_out, int out_size) {
    (void)in_sizes; (void)n_in; (void)out_size;
    const float* preds = (const float*)d_in[0];
    float* out = (float*)d_out;

    cudaFuncSetAttribute(select_kernel,
                         cudaFuncAttributeMaxDynamicSharedMemorySize, SEL_SMEM);

    dim3 dgrid((NANCH + 255) / 256, NB);
    decode_kernel<<<dgrid, 256>>>(preds);
    select_kernel<<<NB, 1024, SEL_SMEM>>>();
    supbuild_kernel<<<dim3(8, NB), 1024>>>();
    resolve_kernel<<<NB, 1024>>>(out);
}